// round 2
// baseline (speedup 1.0000x reference)
#include <cuda_runtime.h>
#include <math.h>

// Problem constants
#define T_STEPS 512
#define BATCH   64
#define HID     1024
#define G4      4096
#define KDIM    1024
#define TBH     ((size_t)T_STEPS * BATCH * HID)   // 512*64*1024
#define SCAN_GRID 128

typedef unsigned long long ull;

// ---------------- device scratch (static, no allocation) ----------------
__device__ float g_X0[(size_t)T_STEPS * BATCH * G4];   // x@Wx^T (reused for layer 1)
__device__ float g_H0[TBH];                             // layer-0 hidden history
__device__ unsigned g_ctr = 0;                          // monotonic barrier counter (never reset)

// ---------------- f32x2 packed-FMA helpers ----------------
__device__ __forceinline__ ull pack2(float lo, float hi) {
    ull r; asm("mov.b64 %0, {%1, %2};" : "=l"(r) : "f"(lo), "f"(hi)); return r;
}
__device__ __forceinline__ ull ffma2(ull a, ull b, ull c) {
    ull d; asm("fma.rn.f32x2 %0, %1, %2, %3;" : "=l"(d) : "l"(a), "l"(b), "l"(c)); return d;
}
__device__ __forceinline__ float2 unpack2(ull v) {
    float2 f; asm("mov.b64 {%0, %1}, %2;" : "=f"(f.x), "=f"(f.y) : "l"(v)); return f;
}
__device__ __forceinline__ float sigmoidf_(float x) { return 1.0f / (1.0f + expf(-x)); }

// =====================================================================
// Big GEMM: C[M,4096] = A[M,1024] @ W[4096,1024]^T   (C = g_X0)
// BM=128, BN=64, BK=16, 256 threads, thread tile 8m x 4n (f32x2 along n)
// =====================================================================
__global__ void gemm_xw_kernel(const float* __restrict__ Aext,
                               const float* __restrict__ W,
                               int use_h0) {
    const float* A = use_h0 ? g_H0 : Aext;
    __shared__ __align__(16) float As[16][132];
    __shared__ __align__(16) float Bs[16][68];

    int tid = threadIdx.x;
    int tx = tid & 15;            // n group (4 cols each)
    int ty = tid >> 4;            // m group (8 rows each)
    int n0 = blockIdx.x * 64;
    size_t m0 = (size_t)blockIdx.y * 128;

    ull acc[8][2];
#pragma unroll
    for (int i = 0; i < 8; i++) { acc[i][0] = 0ULL; acc[i][1] = 0ULL; }

    int ar = tid >> 1;            // 0..127
    int ac = (tid & 1) * 8;       // 0 or 8
    int wr = tid >> 2;            // 0..63
    int wc = (tid & 3) * 4;       // 0,4,8,12

    for (int k0 = 0; k0 < KDIM; k0 += 16) {
        {
            const float* ap = A + (m0 + ar) * KDIM + k0 + ac;
            float4 v0 = *(const float4*)ap;
            float4 v1 = *(const float4*)(ap + 4);
            As[ac + 0][ar] = v0.x; As[ac + 1][ar] = v0.y;
            As[ac + 2][ar] = v0.z; As[ac + 3][ar] = v0.w;
            As[ac + 4][ar] = v1.x; As[ac + 5][ar] = v1.y;
            As[ac + 6][ar] = v1.z; As[ac + 7][ar] = v1.w;
        }
        {
            float4 v = *(const float4*)(W + (size_t)(n0 + wr) * KDIM + k0 + wc);
            Bs[wc + 0][wr] = v.x; Bs[wc + 1][wr] = v.y;
            Bs[wc + 2][wr] = v.z; Bs[wc + 3][wr] = v.w;
        }
        __syncthreads();

#pragma unroll
        for (int kk = 0; kk < 16; kk++) {
            ull b0 = *(const ull*)&Bs[kk][tx * 4];
            ull b1 = *(const ull*)&Bs[kk][tx * 4 + 2];
#pragma unroll
            for (int i = 0; i < 8; i++) {
                float a = As[kk][ty * 8 + i];
                ull pa = pack2(a, a);
                acc[i][0] = ffma2(b0, pa, acc[i][0]);
                acc[i][1] = ffma2(b1, pa, acc[i][1]);
            }
        }
        __syncthreads();
    }

#pragma unroll
    for (int i = 0; i < 8; i++) {
        size_t row = m0 + ty * 8 + i;
        float2 v0 = unpack2(acc[i][0]);
        float2 v1 = unpack2(acc[i][1]);
        float4 o; o.x = v0.x; o.y = v0.y; o.z = v1.x; o.w = v1.y;
        *(float4*)(g_X0 + row * G4 + n0 + tx * 4) = o;
    }
}

// =====================================================================
// Persistent scan kernel: one launch runs all 512 steps of one layer.
// 128 blocks x 256 threads, 1 block/SM (co-resident -> software grid barrier).
// Block b owns h-columns [8b, 8b+8) -> 32 gate rows. Wh slice (32x1024,
// 128KB) lives in smem for the whole scan. c-state lives in registers.
// smem: Ws4 [256 k4][32 lane] float4 (128KB) | hs[64][128] (32KB) | Gs[64][33]
// =====================================================================
#define SCAN_SMEM (131072 + 32768 + 64*33*4)

__global__ void scan_kernel(const float* __restrict__ Wh,
                            float* __restrict__ out,
                            int layer) {
    extern __shared__ float smem[];
    float4* Ws4 = (float4*)smem;               // [k4*32 + lane]
    float*  hs  = smem + 32768;                 // [b*128 + k]
    float*  Gs  = hs + 64 * 128;                // [b*33 + lane]

    float* hist = layer ? out : g_H0;           // h history [t][b][1024]
    float* tail_h = out + TBH + (size_t)layer * 65536;
    float* tail_c = out + TBH + 131072 + (size_t)layer * 65536;

    int tid  = threadIdx.x;
    int lane = tid & 31;
    int w    = tid >> 5;                        // warp 0..7
    int hc0  = blockIdx.x * 8;
    int b0   = w * 8;                           // 8 batches per warp
    int nrow = (lane >> 3) * 1024 + hc0 + (lane & 7);   // global gate row

    // ---- preload Wh slice into smem (once) ----
    {
        int r  = tid >> 3;                                   // local row 0..31
        int nr = (r >> 3) * 1024 + hc0 + (r & 7);
        const float* wp = Wh + (size_t)nr * KDIM;
#pragma unroll
        for (int i = 0; i < 32; i++) {
            int k4 = (tid & 7) + i * 8;
            Ws4[k4 * 32 + r] = *(const float4*)(wp + k4 * 4);
        }
    }

    // ---- cell-state registers: thread handles elems tid and tid+256 ----
    float creg0 = 0.0f, creg1 = 0.0f;
    int cb0 = tid >> 3,        cc0 = tid & 7;
    int cb1 = (tid + 256) >> 3, cc1 = tid & 7;
    __syncthreads();

    for (int t = 0; t < T_STEPS; t++) {
        ull acc[8];
#pragma unroll
        for (int j = 0; j < 8; j++) acc[j] = 0ULL;

        if (t > 0) {
            // ---- grid barrier: wait until all blocks finished step t-1 ----
            __syncthreads();
            if (tid == 0) {
                __threadfence();
                unsigned old = atomicAdd(&g_ctr, 1u);
                unsigned target = (old / SCAN_GRID + 1u) * SCAN_GRID;
                while (*((volatile unsigned*)&g_ctr) < target) __nanosleep(64);
                __threadfence();
            }
            __syncthreads();

            const float* h = hist + (size_t)(t - 1) * 65536;
            int kq = tid & 31;          // k4 within chunk
            int bb = tid >> 5;          // base row for staging

            for (int ch = 0; ch < 8; ch++) {
                // stage h[0:64][ch*128 .. +128) into hs (coalesced)
#pragma unroll
                for (int j = 0; j < 8; j++) {
                    int b = bb + j * 8;
                    *(float4*)&hs[b * 128 + kq * 4] =
                        *(const float4*)&h[b * 1024 + ch * 128 + kq * 4];
                }
                __syncthreads();
#pragma unroll 4
                for (int k4 = 0; k4 < 32; k4++) {
                    float4 wv = Ws4[(ch * 32 + k4) * 32 + lane];
                    ull w01 = pack2(wv.x, wv.y);
                    ull w23 = pack2(wv.z, wv.w);
#pragma unroll
                    for (int j = 0; j < 8; j++) {
                        float4 hv = *(const float4*)&hs[(b0 + j) * 128 + k4 * 4];
                        acc[j] = ffma2(pack2(hv.x, hv.y), w01, acc[j]);
                        acc[j] = ffma2(pack2(hv.z, hv.w), w23, acc[j]);
                    }
                }
                __syncthreads();
            }
        }

        // ---- gate pre-activations -> Gs (add X precompute) ----
        const float* Xt = g_X0 + (size_t)t * BATCH * G4;
#pragma unroll
        for (int j = 0; j < 8; j++) {
            float2 s = unpack2(acc[j]);
            Gs[(b0 + j) * 33 + lane] = s.x + s.y + Xt[(size_t)(b0 + j) * G4 + nrow];
        }
        __syncthreads();

        // ---- fused LSTM cell (2 elements per thread, c in registers) ----
        {
            float gi = Gs[cb0 * 33 + cc0];
            float gj = Gs[cb0 * 33 + 8 + cc0];
            float gf = Gs[cb0 * 33 + 16 + cc0];
            float go = Gs[cb0 * 33 + 24 + cc0];
            float cn = creg0 * sigmoidf_(gf + 1.0f) + sigmoidf_(gi) * tanhf(gj);
            float hn = sigmoidf_(go) * tanhf(cn);
            creg0 = cn;
            int col = hc0 + cc0;
            hist[(size_t)t * 65536 + cb0 * 1024 + col] = hn;
            if (t == T_STEPS - 1) {
                tail_h[cb0 * 1024 + col] = hn;
                tail_c[cb0 * 1024 + col] = cn;
            }
        }
        {
            float gi = Gs[cb1 * 33 + cc1];
            float gj = Gs[cb1 * 33 + 8 + cc1];
            float gf = Gs[cb1 * 33 + 16 + cc1];
            float go = Gs[cb1 * 33 + 24 + cc1];
            float cn = creg1 * sigmoidf_(gf + 1.0f) + sigmoidf_(gi) * tanhf(gj);
            float hn = sigmoidf_(go) * tanhf(cn);
            creg1 = cn;
            int col = hc0 + cc1;
            hist[(size_t)t * 65536 + cb1 * 1024 + col] = hn;
            if (t == T_STEPS - 1) {
                tail_h[cb1 * 1024 + col] = hn;
                tail_c[cb1 * 1024 + col] = cn;
            }
        }
        __syncthreads();
    }
}

// =====================================================================
// launch: 4 graph nodes total
// =====================================================================
extern "C" void kernel_launch(void* const* d_in, const int* in_sizes, int n_in,
                              void* d_out, int out_size) {
    const float* x   = (const float*)d_in[0];
    const float* Wx0 = (const float*)d_in[1];
    const float* Wh0 = (const float*)d_in[2];
    const float* Wx1 = (const float*)d_in[3];
    const float* Wh1 = (const float*)d_in[4];
    float* out = (float*)d_out;

    cudaFuncSetAttribute(scan_kernel,
                         cudaFuncAttributeMaxDynamicSharedMemorySize, SCAN_SMEM);

    dim3 ggrid(G4 / 64, (T_STEPS * BATCH) / 128);   // 64 x 256

    gemm_xw_kernel<<<ggrid, 256>>>(x, Wx0, 0);        // X0 = x @ Wx0^T
    scan_kernel<<<SCAN_GRID, 256, SCAN_SMEM>>>(Wh0, out, 0);
    gemm_xw_kernel<<<ggrid, 256>>>(nullptr, Wx1, 1);  // X1 = H0 @ Wx1^T
    scan_kernel<<<SCAN_GRID, 256, SCAN_SMEM>>>(Wh1, out, 1);
}

// round 3
// speedup vs baseline: 1.0503x; 1.0503x over previous
#include <cuda_runtime.h>
#include <math.h>

// Problem constants
#define T_STEPS 512
#define BATCH   64
#define HID     1024
#define G4      4096
#define KDIM    1024
#define TBH     ((size_t)T_STEPS * BATCH * HID)   // 512*64*1024
#define SCAN_GRID 128

typedef unsigned long long ull;

// ---------------- device scratch (static, no allocation) ----------------
__device__ float g_X0[(size_t)T_STEPS * BATCH * G4];   // x@Wx^T (reused for layer 1)
__device__ float g_H0[TBH];                             // layer-0 hidden history
__device__ unsigned g_ctr = 0;                          // monotonic barrier counter (never reset)

// ---------------- f32x2 packed-FMA helpers ----------------
__device__ __forceinline__ ull pack2(float lo, float hi) {
    ull r; asm("mov.b64 %0, {%1, %2};" : "=l"(r) : "f"(lo), "f"(hi)); return r;
}
__device__ __forceinline__ ull ffma2(ull a, ull b, ull c) {
    ull d; asm("fma.rn.f32x2 %0, %1, %2, %3;" : "=l"(d) : "l"(a), "l"(b), "l"(c)); return d;
}
__device__ __forceinline__ float2 unpack2(ull v) {
    float2 f; asm("mov.b64 {%0, %1}, %2;" : "=f"(f.x), "=f"(f.y) : "l"(v)); return f;
}
__device__ __forceinline__ float sigmoidf_(float x) { return 1.0f / (1.0f + expf(-x)); }

// =====================================================================
// Big GEMM: C[M,4096] = A[M,1024] @ W[4096,1024]^T   (C = g_X0)
// BM=128, BN=64, BK=16, 256 threads, thread tile 8m x 4n (f32x2 along n)
// =====================================================================
__global__ void gemm_xw_kernel(const float* __restrict__ Aext,
                               const float* __restrict__ W,
                               int use_h0) {
    const float* A = use_h0 ? g_H0 : Aext;
    __shared__ __align__(16) float As[16][132];
    __shared__ __align__(16) float Bs[16][68];

    int tid = threadIdx.x;
    int tx = tid & 15;            // n group (4 cols each)
    int ty = tid >> 4;            // m group (8 rows each)
    int n0 = blockIdx.x * 64;
    size_t m0 = (size_t)blockIdx.y * 128;

    ull acc[8][2];
#pragma unroll
    for (int i = 0; i < 8; i++) { acc[i][0] = 0ULL; acc[i][1] = 0ULL; }

    int ar = tid >> 1;            // 0..127
    int ac = (tid & 1) * 8;       // 0 or 8
    int wr = tid >> 2;            // 0..63
    int wc = (tid & 3) * 4;       // 0,4,8,12

    for (int k0 = 0; k0 < KDIM; k0 += 16) {
        {
            const float* ap = A + (m0 + ar) * KDIM + k0 + ac;
            float4 v0 = *(const float4*)ap;
            float4 v1 = *(const float4*)(ap + 4);
            As[ac + 0][ar] = v0.x; As[ac + 1][ar] = v0.y;
            As[ac + 2][ar] = v0.z; As[ac + 3][ar] = v0.w;
            As[ac + 4][ar] = v1.x; As[ac + 5][ar] = v1.y;
            As[ac + 6][ar] = v1.z; As[ac + 7][ar] = v1.w;
        }
        {
            float4 v = *(const float4*)(W + (size_t)(n0 + wr) * KDIM + k0 + wc);
            Bs[wc + 0][wr] = v.x; Bs[wc + 1][wr] = v.y;
            Bs[wc + 2][wr] = v.z; Bs[wc + 3][wr] = v.w;
        }
        __syncthreads();

#pragma unroll
        for (int kk = 0; kk < 16; kk++) {
            ull b0 = *(const ull*)&Bs[kk][tx * 4];
            ull b1 = *(const ull*)&Bs[kk][tx * 4 + 2];
#pragma unroll
            for (int i = 0; i < 8; i++) {
                float a = As[kk][ty * 8 + i];
                ull pa = pack2(a, a);
                acc[i][0] = ffma2(b0, pa, acc[i][0]);
                acc[i][1] = ffma2(b1, pa, acc[i][1]);
            }
        }
        __syncthreads();
    }

#pragma unroll
    for (int i = 0; i < 8; i++) {
        size_t row = m0 + ty * 8 + i;
        float2 v0 = unpack2(acc[i][0]);
        float2 v1 = unpack2(acc[i][1]);
        float4 o; o.x = v0.x; o.y = v0.y; o.z = v1.x; o.w = v1.y;
        *(float4*)(g_X0 + row * G4 + n0 + tx * 4) = o;
    }
}

// =====================================================================
// Persistent scan kernel: one launch runs all 512 steps of one layer.
// 128 blocks x 256 threads, 1 block/SM (co-resident -> software grid barrier).
// Block b owns h-columns [8b, 8b+8) -> 32 gate rows. Wh slice (32x1024,
// 128KB) lives in smem for the whole scan. c-state lives in registers.
// smem: Ws4 [256 k4][32 lane] float4 (128KB) | hs[64][128] (32KB) | Gs[64][33]
// =====================================================================
#define SCAN_SMEM (131072 + 32768 + 64*33*4)

__global__ void scan_kernel(const float* __restrict__ Wh,
                            float* __restrict__ out,
                            int layer) {
    extern __shared__ float smem[];
    float4* Ws4 = (float4*)smem;               // [k4*32 + lane]
    float*  hs  = smem + 32768;                 // [b*128 + k]
    float*  Gs  = hs + 64 * 128;                // [b*33 + lane]

    float* hist = layer ? out : g_H0;           // h history [t][b][1024]
    float* tail_h = out + TBH + (size_t)layer * 65536;
    float* tail_c = out + TBH + 131072 + (size_t)layer * 65536;

    int tid  = threadIdx.x;
    int lane = tid & 31;
    int w    = tid >> 5;                        // warp 0..7
    int hc0  = blockIdx.x * 8;
    int b0   = w * 8;                           // 8 batches per warp
    int nrow = (lane >> 3) * 1024 + hc0 + (lane & 7);   // global gate row

    // ---- preload Wh slice into smem (once) ----
    {
        int r  = tid >> 3;                                   // local row 0..31
        int nr = (r >> 3) * 1024 + hc0 + (r & 7);
        const float* wp = Wh + (size_t)nr * KDIM;
#pragma unroll
        for (int i = 0; i < 32; i++) {
            int k4 = (tid & 7) + i * 8;
            Ws4[k4 * 32 + r] = *(const float4*)(wp + k4 * 4);
        }
    }

    // ---- cell-state registers: thread handles elems tid and tid+256 ----
    float creg0 = 0.0f, creg1 = 0.0f;
    int cb0 = tid >> 3,        cc0 = tid & 7;
    int cb1 = (tid + 256) >> 3, cc1 = tid & 7;
    __syncthreads();

    for (int t = 0; t < T_STEPS; t++) {
        ull acc[8];
#pragma unroll
        for (int j = 0; j < 8; j++) acc[j] = 0ULL;

        if (t > 0) {
            // ---- grid barrier: wait until all blocks finished step t-1 ----
            __syncthreads();
            if (tid == 0) {
                __threadfence();
                unsigned old = atomicAdd(&g_ctr, 1u);
                unsigned target = (old / SCAN_GRID + 1u) * SCAN_GRID;
                while (*((volatile unsigned*)&g_ctr) < target) __nanosleep(64);
                __threadfence();
            }
            __syncthreads();

            const float* h = hist + (size_t)(t - 1) * 65536;
            int kq = tid & 31;          // k4 within chunk
            int bb = tid >> 5;          // base row for staging

            for (int ch = 0; ch < 8; ch++) {
                // stage h[0:64][ch*128 .. +128) into hs (coalesced)
#pragma unroll
                for (int j = 0; j < 8; j++) {
                    int b = bb + j * 8;
                    *(float4*)&hs[b * 128 + kq * 4] =
                        *(const float4*)&h[b * 1024 + ch * 128 + kq * 4];
                }
                __syncthreads();
#pragma unroll 4
                for (int k4 = 0; k4 < 32; k4++) {
                    float4 wv = Ws4[(ch * 32 + k4) * 32 + lane];
                    ull w01 = pack2(wv.x, wv.y);
                    ull w23 = pack2(wv.z, wv.w);
#pragma unroll
                    for (int j = 0; j < 8; j++) {
                        float4 hv = *(const float4*)&hs[(b0 + j) * 128 + k4 * 4];
                        acc[j] = ffma2(pack2(hv.x, hv.y), w01, acc[j]);
                        acc[j] = ffma2(pack2(hv.z, hv.w), w23, acc[j]);
                    }
                }
                __syncthreads();
            }
        }

        // ---- gate pre-activations -> Gs (add X precompute) ----
        const float* Xt = g_X0 + (size_t)t * BATCH * G4;
#pragma unroll
        for (int j = 0; j < 8; j++) {
            float2 s = unpack2(acc[j]);
            Gs[(b0 + j) * 33 + lane] = s.x + s.y + Xt[(size_t)(b0 + j) * G4 + nrow];
        }
        __syncthreads();

        // ---- fused LSTM cell (2 elements per thread, c in registers) ----
        {
            float gi = Gs[cb0 * 33 + cc0];
            float gj = Gs[cb0 * 33 + 8 + cc0];
            float gf = Gs[cb0 * 33 + 16 + cc0];
            float go = Gs[cb0 * 33 + 24 + cc0];
            float cn = creg0 * sigmoidf_(gf + 1.0f) + sigmoidf_(gi) * tanhf(gj);
            float hn = sigmoidf_(go) * tanhf(cn);
            creg0 = cn;
            int col = hc0 + cc0;
            hist[(size_t)t * 65536 + cb0 * 1024 + col] = hn;
            if (t == T_STEPS - 1) {
                tail_h[cb0 * 1024 + col] = hn;
                tail_c[cb0 * 1024 + col] = cn;
            }
        }
        {
            float gi = Gs[cb1 * 33 + cc1];
            float gj = Gs[cb1 * 33 + 8 + cc1];
            float gf = Gs[cb1 * 33 + 16 + cc1];
            float go = Gs[cb1 * 33 + 24 + cc1];
            float cn = creg1 * sigmoidf_(gf + 1.0f) + sigmoidf_(gi) * tanhf(gj);
            float hn = sigmoidf_(go) * tanhf(cn);
            creg1 = cn;
            int col = hc0 + cc1;
            hist[(size_t)t * 65536 + cb1 * 1024 + col] = hn;
            if (t == T_STEPS - 1) {
                tail_h[cb1 * 1024 + col] = hn;
                tail_c[cb1 * 1024 + col] = cn;
            }
        }
        __syncthreads();
    }
}

// =====================================================================
// launch: 4 graph nodes total
// =====================================================================
extern "C" void kernel_launch(void* const* d_in, const int* in_sizes, int n_in,
                              void* d_out, int out_size) {
    const float* x   = (const float*)d_in[0];
    const float* Wx0 = (const float*)d_in[1];
    const float* Wh0 = (const float*)d_in[2];
    const float* Wx1 = (const float*)d_in[3];
    const float* Wh1 = (const float*)d_in[4];
    float* out = (float*)d_out;

    cudaFuncSetAttribute(scan_kernel,
                         cudaFuncAttributeMaxDynamicSharedMemorySize, SCAN_SMEM);

    dim3 ggrid(G4 / 64, (T_STEPS * BATCH) / 128);   // 64 x 256

    gemm_xw_kernel<<<ggrid, 256>>>(x, Wx0, 0);        // X0 = x @ Wx0^T
    scan_kernel<<<SCAN_GRID, 256, SCAN_SMEM>>>(Wh0, out, 0);
    gemm_xw_kernel<<<ggrid, 256>>>(nullptr, Wx1, 1);  // X1 = H0 @ Wx1^T
    scan_kernel<<<SCAN_GRID, 256, SCAN_SMEM>>>(Wh1, out, 1);
}

// round 6
// speedup vs baseline: 1.4505x; 1.3810x over previous
#include <cuda_runtime.h>
#include <math.h>

#define T_STEPS 512
#define BATCH   64
#define HID     1024
#define G4      4096
#define KDIM    1024
#define TBH     ((size_t)T_STEPS * BATCH * HID)
#define SCAN_GRID 128

typedef unsigned long long ull;

__device__ float g_X0[(size_t)T_STEPS * BATCH * G4];   // gate precompute
__device__ float g_H0[TBH];                             // layer-0 h history
__device__ float g_hT[2 * BATCH * HID];                 // transposed h ping-pong [k][b]
__device__ unsigned g_ctr = 0;                          // monotonic barrier counter

__device__ __forceinline__ ull pack2(float lo, float hi) {
    ull r; asm("mov.b64 %0, {%1, %2};" : "=l"(r) : "f"(lo), "f"(hi)); return r;
}
__device__ __forceinline__ ull ffma2(ull a, ull b, ull c) {
    ull d; asm("fma.rn.f32x2 %0, %1, %2, %3;" : "=l"(d) : "l"(a), "l"(b), "l"(c)); return d;
}
__device__ __forceinline__ float2 unpack2(ull v) {
    float2 f; asm("mov.b64 {%0, %1}, %2;" : "=f"(f.x), "=f"(f.y) : "l"(v)); return f;
}
__device__ __forceinline__ float sigmoidf_(float x) { return 1.0f / (1.0f + expf(-x)); }
__device__ __forceinline__ unsigned smem_u32(const void* p) {
    unsigned a;
    asm("{ .reg .u64 t; cvta.to.shared.u64 t, %1; cvt.u32.u64 %0, t; }" : "=r"(a) : "l"(p));
    return a;
}
__device__ __forceinline__ void cp16(unsigned dst, const void* src) {
    asm volatile("cp.async.cg.shared.global [%0], [%1], 16;" :: "r"(dst), "l"(src));
}
__device__ __forceinline__ void cp_commit() { asm volatile("cp.async.commit_group;"); }
template<int N> __device__ __forceinline__ void cp_wait() {
    asm volatile("cp.async.wait_group %0;" :: "n"(N));
}

// =====================================================================
// PROVEN fp32 GEMM (ran in the 41.9ms pass): C[M,4096] = A @ W^T
// BM=128, BN=64, BK=16, 256 threads, 8m x 4n per thread via f32x2.
// =====================================================================
__global__ void gemm_xw_kernel(const float* __restrict__ Aext,
                               const float* __restrict__ W,
                               int use_h0) {
    const float* A = use_h0 ? g_H0 : Aext;
    __shared__ __align__(16) float As[16][132];
    __shared__ __align__(16) float Bs[16][68];

    int tid = threadIdx.x;
    int tx = tid & 15;
    int ty = tid >> 4;
    int n0 = blockIdx.x * 64;
    size_t m0 = (size_t)blockIdx.y * 128;

    ull acc[8][2];
#pragma unroll
    for (int i = 0; i < 8; i++) { acc[i][0] = 0ULL; acc[i][1] = 0ULL; }

    int ar = tid >> 1, ac = (tid & 1) * 8;
    int wr = tid >> 2, wc = (tid & 3) * 4;

    for (int k0 = 0; k0 < KDIM; k0 += 16) {
        {
            const float* ap = A + (m0 + ar) * KDIM + k0 + ac;
            float4 v0 = *(const float4*)ap;
            float4 v1 = *(const float4*)(ap + 4);
            As[ac + 0][ar] = v0.x; As[ac + 1][ar] = v0.y;
            As[ac + 2][ar] = v0.z; As[ac + 3][ar] = v0.w;
            As[ac + 4][ar] = v1.x; As[ac + 5][ar] = v1.y;
            As[ac + 6][ar] = v1.z; As[ac + 7][ar] = v1.w;
        }
        {
            float4 v = *(const float4*)(W + (size_t)(n0 + wr) * KDIM + k0 + wc);
            Bs[wc + 0][wr] = v.x; Bs[wc + 1][wr] = v.y;
            Bs[wc + 2][wr] = v.z; Bs[wc + 3][wr] = v.w;
        }
        __syncthreads();

#pragma unroll
        for (int kk = 0; kk < 16; kk++) {
            ull b0 = *(const ull*)&Bs[kk][tx * 4];
            ull b1 = *(const ull*)&Bs[kk][tx * 4 + 2];
#pragma unroll
            for (int i = 0; i < 8; i++) {
                float a = As[kk][ty * 8 + i];
                ull pa = pack2(a, a);
                acc[i][0] = ffma2(b0, pa, acc[i][0]);
                acc[i][1] = ffma2(b1, pa, acc[i][1]);
            }
        }
        __syncthreads();
    }

#pragma unroll
    for (int i = 0; i < 8; i++) {
        size_t row = m0 + ty * 8 + i;
        float2 v0 = unpack2(acc[i][0]);
        float2 v1 = unpack2(acc[i][1]);
        float4 o; o.x = v0.x; o.y = v0.y; o.z = v1.x; o.w = v1.y;
        *(float4*)(g_X0 + row * G4 + n0 + tx * 4) = o;
    }
}

// =====================================================================
// NEW persistent scan. 128 blocks x 256 thr, 1 block/SM.
// W resident [k][n] 128KB. h prev: transposed global ping-pong g_hT [k][b],
// cp.async double-buffered. X prefetched via cp.async. Thread tile 4n x 8b,
// 4-way k-slice + smem reduce. Proven single-counter barrier.
// =====================================================================
#define SCAN_SMEM (131072 + 65536 + 32*68*4 + 8192)
__global__ __launch_bounds__(256, 1) void scan_kernel(const float* __restrict__ Wh,
                                                      float* __restrict__ out,
                                                      int layer) {
    extern __shared__ float sm[];
    float* Ws    = sm;                         // [1024][32]
    float* hsbuf = sm + 32768;                 // 2 x [128][64]
    float* Gs    = sm + 32768 + 16384;         // [32][68]
    float* sX    = sm + 32768 + 16384 + 32*68; // [64][32]
    unsigned hs_u32 = smem_u32(hsbuf);
    unsigned sx_u32 = smem_u32(sX);

    float* hist   = layer ? out : g_H0;
    float* tail_h = out + TBH + (size_t)layer * 65536;
    float* tail_c = out + TBH + 131072 + (size_t)layer * 65536;

    int tid = threadIdx.x;
    int hc0 = blockIdx.x * 8;
    int ks  = tid >> 6;
    int pos = tid & 63;
    int png = pos & 7, pbg = pos >> 3;
    int cc  = tid & 7, cb0 = tid >> 3, cb1 = cb0 + 32;
    float creg0 = 0.0f, creg1 = 0.0f;

    {   // preload Ws[k*32 + r] = Wh[rowg(r)][k]
        int rl = tid >> 3, kq = tid & 7;
        int rg = (rl >> 3) * 1024 + hc0 + (rl & 7);
        const float* wp = Wh + (size_t)rg * KDIM;
#pragma unroll
        for (int i = 0; i < 32; i++) {
            int k = i * 32 + kq * 4;
            float4 v = *(const float4*)(wp + k);
            Ws[(k + 0) * 32 + rl] = v.x; Ws[(k + 1) * 32 + rl] = v.y;
            Ws[(k + 2) * 32 + rl] = v.z; Ws[(k + 3) * 32 + rl] = v.w;
        }
    }
    __syncthreads();

    for (int t = 0; t < T_STEPS; t++) {
        ull acc[4][4];
#pragma unroll
        for (int i = 0; i < 4; i++)
#pragma unroll
            for (int j = 0; j < 4; j++) acc[i][j] = 0ULL;

        if (t > 0) {
            // proven monotonic grid barrier
            __syncthreads();
            if (tid == 0) {
                __threadfence();
                unsigned old = atomicAdd(&g_ctr, 1u);
                unsigned target = (old / SCAN_GRID + 1u) * SCAN_GRID;
                while (*((volatile unsigned*)&g_ctr) < target) __nanosleep(64);
                __threadfence();
            }
            __syncthreads();
        }

        // prefetch X slice for this step into sX[b*32 + localrow]
        const float* Xt = g_X0 + (size_t)t * 64 * G4;
#pragma unroll
        for (int i = 0; i < 2; i++) {
            int u = tid + i * 256;
            int b = u >> 3, g = (u >> 1) & 3, hf = u & 1;
            cp16(sx_u32 + (unsigned)(b * 128 + g * 32 + hf * 16),
                 Xt + (size_t)b * G4 + g * 1024 + hc0 + hf * 4);
        }

        if (t > 0) {
            const float* hprev = g_hT + ((t + 1) & 1) * 65536;
#pragma unroll
            for (int i = 0; i < 8; i++) {
                int u = tid + i * 256;
                cp16(hs_u32 + u * 16, hprev + u * 4);
            }
            cp_commit();

            for (int ch = 0; ch < 8; ch++) {
                if (ch + 1 < 8) {
                    int buf = (ch + 1) & 1;
#pragma unroll
                    for (int i = 0; i < 8; i++) {
                        int u = tid + i * 256;
                        cp16(hs_u32 + buf * 32768 + u * 16, hprev + (ch + 1) * 8192 + u * 4);
                    }
                    cp_commit();
                    cp_wait<1>();
                } else cp_wait<0>();
                __syncthreads();

                const float* hb = hsbuf + (ch & 1) * 8192;
                const float* wb = Ws + ch * 128 * 32;
#pragma unroll 4
                for (int kk = 0; kk < 32; kk++) {
                    int k = ks * 32 + kk;
                    float4 w4 = *(const float4*)(wb + k * 32 + png * 4);
                    const float* hp = hb + k * 64 + pbg * 8;
                    float4 h0 = *(const float4*)hp;
                    float4 h1 = *(const float4*)(hp + 4);
                    ull hp0 = pack2(h0.x, h0.y), hp1 = pack2(h0.z, h0.w);
                    ull hp2 = pack2(h1.x, h1.y), hp3 = pack2(h1.z, h1.w);
                    ull w0 = pack2(w4.x, w4.x), w1 = pack2(w4.y, w4.y);
                    ull w2 = pack2(w4.z, w4.z), w3 = pack2(w4.w, w4.w);
                    acc[0][0] = ffma2(hp0, w0, acc[0][0]); acc[0][1] = ffma2(hp1, w0, acc[0][1]);
                    acc[0][2] = ffma2(hp2, w0, acc[0][2]); acc[0][3] = ffma2(hp3, w0, acc[0][3]);
                    acc[1][0] = ffma2(hp0, w1, acc[1][0]); acc[1][1] = ffma2(hp1, w1, acc[1][1]);
                    acc[1][2] = ffma2(hp2, w1, acc[1][2]); acc[1][3] = ffma2(hp3, w1, acc[1][3]);
                    acc[2][0] = ffma2(hp0, w2, acc[2][0]); acc[2][1] = ffma2(hp1, w2, acc[2][1]);
                    acc[2][2] = ffma2(hp2, w2, acc[2][2]); acc[2][3] = ffma2(hp3, w2, acc[2][3]);
                    acc[3][0] = ffma2(hp0, w3, acc[3][0]); acc[3][1] = ffma2(hp1, w3, acc[3][1]);
                    acc[3][2] = ffma2(hp2, w3, acc[3][2]); acc[3][3] = ffma2(hp3, w3, acc[3][3]);
                }
                __syncthreads();
            }
        } else {
            cp_commit();
            cp_wait<0>();
            __syncthreads();
        }

        // reduce 4 k-slices through smem (reuse hsbuf)
        ull* scr = (ull*)hsbuf;
        if (ks > 0) {
            int base = ((ks - 1) * 64 + pos) * 16;
#pragma unroll
            for (int i = 0; i < 4; i++)
#pragma unroll
                for (int j = 0; j < 4; j++) scr[base + i * 4 + j] = acc[i][j];
        }
        __syncthreads();
        if (ks == 0) {
#pragma unroll
            for (int i = 0; i < 4; i++) {
                int rl = png * 4 + i;
#pragma unroll
                for (int j = 0; j < 4; j++) {
                    float2 s = unpack2(acc[i][j]);
#pragma unroll
                    for (int sl = 0; sl < 3; sl++) {
                        float2 p = unpack2(scr[(sl * 64 + pos) * 16 + i * 4 + j]);
                        s.x += p.x; s.y += p.y;
                    }
                    int b = pbg * 8 + j * 2;
                    Gs[rl * 68 + b]     = s.x + sX[b * 32 + rl];
                    Gs[rl * 68 + b + 1] = s.y + sX[(b + 1) * 32 + rl];
                }
            }
        }
        __syncthreads();

        // fused cell: 2 elements per thread
#pragma unroll
        for (int e = 0; e < 2; e++) {
            int cb = e ? cb1 : cb0;
            float& creg = e ? creg1 : creg0;
            float gi = Gs[(cc) * 68 + cb];
            float gj = Gs[(8 + cc) * 68 + cb];
            float gf = Gs[(16 + cc) * 68 + cb];
            float go = Gs[(24 + cc) * 68 + cb];
            float cn = creg * sigmoidf_(gf + 1.0f) + sigmoidf_(gi) * tanhf(gj);
            float hn = sigmoidf_(go) * tanhf(cn);
            creg = cn;
            int col = hc0 + cc;
            hist[(size_t)t * 65536 + cb * 1024 + col] = hn;
            g_hT[(t & 1) * 65536 + col * 64 + cb] = hn;
            if (t == T_STEPS - 1) {
                tail_h[cb * 1024 + col] = hn;
                tail_c[cb * 1024 + col] = cn;
            }
        }
        __syncthreads();
    }
}

extern "C" void kernel_launch(void* const* d_in, const int* in_sizes, int n_in,
                              void* d_out, int out_size) {
    const float* x   = (const float*)d_in[0];
    const float* Wx0 = (const float*)d_in[1];
    const float* Wh0 = (const float*)d_in[2];
    const float* Wx1 = (const float*)d_in[3];
    const float* Wh1 = (const float*)d_in[4];
    float* out = (float*)d_out;

    cudaFuncSetAttribute(scan_kernel, cudaFuncAttributeMaxDynamicSharedMemorySize, SCAN_SMEM);

    dim3 ggrid(G4 / 64, (T_STEPS * BATCH) / 128);   // 64 x 256

    gemm_xw_kernel<<<ggrid, 256>>>(x, Wx0, 0);
    scan_kernel<<<SCAN_GRID, 256, SCAN_SMEM>>>(Wh0, out, 0);
    gemm_xw_kernel<<<ggrid, 256>>>(nullptr, Wx1, 1);
    scan_kernel<<<SCAN_GRID, 256, SCAN_SMEM>>>(Wh1, out, 1);
}